// round 1
// baseline (speedup 1.0000x reference)
#include <cuda_runtime.h>

#define P 5

// ---------------- device scratch (no allocations allowed) ----------------
__device__ unsigned g_min_key;
__device__ unsigned g_max_key;
__device__ int      g_counts[P];
__device__ float    g_dmin, g_width;
__device__ float    g_accum[P];
__device__ float    g_grid[P];
__device__ float    g_slope[P - 1];
__device__ float    g_tp[P];
__device__ float    g_vp[P];

// monotone key mapping for float atomics
__device__ __forceinline__ unsigned f2key(float f) {
    unsigned u = __float_as_uint(f);
    return (u & 0x80000000u) ? ~u : (u | 0x80000000u);
}
__device__ __forceinline__ float key2f(unsigned k) {
    unsigned u = (k & 0x80000000u) ? (k ^ 0x80000000u) : ~k;
    return __uint_as_float(u);
}

// ---------------- kernel 0: reset ----------------
__global__ void k_init() {
    if (threadIdx.x == 0) {
        g_min_key = 0xFFFFFFFFu;
        g_max_key = 0u;
    }
    if (threadIdx.x < P) g_counts[threadIdx.x] = 0;
}

// ---------------- kernel 1: global min/max of d = x*c ----------------
__global__ void k_minmax(const float* __restrict__ x,
                         const float* __restrict__ ct, int n) {
    const float c = ct[0];
    float lo = __int_as_float(0x7f800000);   // +inf
    float hi = __int_as_float(0xff800000);   // -inf

    const int nv = n >> 2;
    const float4* __restrict__ x4 = (const float4*)x;
    const int stride = gridDim.x * blockDim.x;
    for (int i = blockIdx.x * blockDim.x + threadIdx.x; i < nv; i += stride) {
        float4 v = x4[i];
        float a = v.x * c, b = v.y * c, d = v.z * c, e = v.w * c;
        lo = fminf(lo, fminf(fminf(a, b), fminf(d, e)));
        hi = fmaxf(hi, fmaxf(fmaxf(a, b), fmaxf(d, e)));
    }
    for (int i = (nv << 2) + blockIdx.x * blockDim.x + threadIdx.x; i < n; i += stride) {
        float d = x[i] * c;
        lo = fminf(lo, d);
        hi = fmaxf(hi, d);
    }

    // warp reduce
    #pragma unroll
    for (int o = 16; o; o >>= 1) {
        lo = fminf(lo, __shfl_xor_sync(0xFFFFFFFFu, lo, o));
        hi = fmaxf(hi, __shfl_xor_sync(0xFFFFFFFFu, hi, o));
    }
    __shared__ float s_lo[8], s_hi[8];
    const int wid = threadIdx.x >> 5, lid = threadIdx.x & 31;
    if (lid == 0) { s_lo[wid] = lo; s_hi[wid] = hi; }
    __syncthreads();
    if (threadIdx.x == 0) {
        const int nw = (blockDim.x + 31) >> 5;
        for (int w = 1; w < nw; ++w) {
            lo = fminf(lo, s_lo[w]);
            hi = fmaxf(hi, s_hi[w]);
        }
        atomicMin(&g_min_key, f2key(lo));
        atomicMax(&g_max_key, f2key(hi));
    }
}

// ---------------- kernel 2: compute dmin/width ----------------
__global__ void k_setupA() {
    float mn = key2f(g_min_key);
    float mx = key2f(g_max_key);
    float dmin = mn - 0.1f;
    float dmax = mx + 0.1f;
    g_dmin = dmin;
    g_width = (dmax - dmin) / (float)P;
}

// ---------------- kernel 3: 5-bin histogram ----------------
__global__ void k_hist(const float* __restrict__ x,
                       const float* __restrict__ ct, int n) {
    const float c = ct[0];
    const float dmin = g_dmin;
    const float width = g_width;

    int c0 = 0, c1 = 0, c2 = 0, c3 = 0, c4 = 0;

    const int nv = n >> 2;
    const float4* __restrict__ x4 = (const float4*)x;
    const int stride = gridDim.x * blockDim.x;
    for (int i = blockIdx.x * blockDim.x + threadIdx.x; i < nv; i += stride) {
        float4 v = x4[i];
        #pragma unroll
        for (int k = 0; k < 4; ++k) {
            float d = ((k == 0) ? v.x : (k == 1) ? v.y : (k == 2) ? v.z : v.w) * c;
            int b = (int)floorf((d - dmin) / width);
            b = min(max(b, 0), P - 1);
            c0 += (b == 0); c1 += (b == 1); c2 += (b == 2);
            c3 += (b == 3); c4 += (b == 4);
        }
    }
    for (int i = (nv << 2) + blockIdx.x * blockDim.x + threadIdx.x; i < n; i += stride) {
        float d = x[i] * c;
        int b = (int)floorf((d - dmin) / width);
        b = min(max(b, 0), P - 1);
        c0 += (b == 0); c1 += (b == 1); c2 += (b == 2);
        c3 += (b == 3); c4 += (b == 4);
    }

    // warp butterfly reduce
    #pragma unroll
    for (int o = 16; o; o >>= 1) {
        c0 += __shfl_xor_sync(0xFFFFFFFFu, c0, o);
        c1 += __shfl_xor_sync(0xFFFFFFFFu, c1, o);
        c2 += __shfl_xor_sync(0xFFFFFFFFu, c2, o);
        c3 += __shfl_xor_sync(0xFFFFFFFFu, c3, o);
        c4 += __shfl_xor_sync(0xFFFFFFFFu, c4, o);
    }
    __shared__ int sh[P];
    if (threadIdx.x < P) sh[threadIdx.x] = 0;
    __syncthreads();
    if ((threadIdx.x & 31) == 0) {
        atomicAdd(&sh[0], c0);
        atomicAdd(&sh[1], c1);
        atomicAdd(&sh[2], c2);
        atomicAdd(&sh[3], c3);
        atomicAdd(&sh[4], c4);
    }
    __syncthreads();
    if (threadIdx.x < P) atomicAdd(&g_counts[threadIdx.x], sh[threadIdx.x]);
}

// ---------------- kernel 4: CDF / frame / parameter tables ----------------
__global__ void k_setupB(const float* __restrict__ params) {
    const float dmin = g_dmin;
    const float width = g_width;

    // float32 scatter-add-of-ones saturates at 2^24 (adding 1.0f at 16777216
    // rounds back). Replicate: min(count, 16777216).
    float cf[P];
    float tot = 0.0f;
    #pragma unroll
    for (int k = 0; k < P; ++k) {
        cf[k] = fminf((float)g_counts[k], 16777216.0f);
        tot += cf[k];
    }

    float accum[P];
    float run = 0.0f;
    #pragma unroll
    for (int k = 0; k < P; ++k) {
        float prob = cf[k] / tot;
        run += prob;
        accum[k] = run * (float)P;
    }

    float grid[P];
    #pragma unroll
    for (int k = 0; k < P; ++k) {
        float e0 = dmin + width * (float)k;
        float e1 = dmin + width * (float)(k + 1);
        grid[k] = 0.5f * (e0 + e1);
    }

    #pragma unroll
    for (int i = 0; i < P - 1; ++i) {
        float den = grid[i + 1] - grid[i];
        g_slope[i] = (accum[i + 1] - accum[i]) / den;
        g_accum[i] = accum[i];
        g_grid[i]  = grid[i];
    }
    g_accum[P - 1] = accum[P - 1];
    g_grid[P - 1]  = grid[P - 1];

    // frame = interp1d(accum, grid, arange(P)), with flat-segment guard
    #pragma unroll
    for (int k = 0; k < P; ++k) {
        float q = (float)k;
        int j = 0;
        while (j < P && accum[j] < q) ++j;   // searchsorted left
        int idx = j - 1;
        idx = min(max(idx, 0), P - 2);
        float x0 = accum[idx], x1 = accum[idx + 1];
        float den = x1 - x0;
        if (den == 0.0f) den = 1.0f;
        float frame = grid[idx] + (grid[idx + 1] - grid[idx]) / den * (q - x0);
        g_tp[k] = frame + 0.001f * params[k];       // theta row
        g_vp[k] = frame + 0.001f * params[P + k];   // velocity row
    }
}

// ---------------- kernel 5: final elementwise transform ----------------
__global__ void k_compute(const float* __restrict__ x,
                          const float* __restrict__ ct,
                          const float* __restrict__ st,
                          float* __restrict__ out, int n) {
    __shared__ float s_accum[P], s_grid[P], s_slope[P - 1], s_tp[P], s_vp[P];
    if (threadIdx.x < P) {
        s_accum[threadIdx.x] = g_accum[threadIdx.x];
        s_grid[threadIdx.x]  = g_grid[threadIdx.x];
        s_tp[threadIdx.x]    = g_tp[threadIdx.x];
        s_vp[threadIdx.x]    = g_vp[threadIdx.x];
        if (threadIdx.x < P - 1) s_slope[threadIdx.x] = g_slope[threadIdx.x];
    }
    __syncthreads();

    const float c  = ct[0];
    const float sp = st[0];
    const float g1 = s_grid[1], g2 = s_grid[2], g3 = s_grid[3];

    const int nv = n >> 2;
    const float4* __restrict__ x4 = (const float4*)x;
    float4* __restrict__ o4 = (float4*)out;
    const int stride = gridDim.x * blockDim.x;

    for (int i = blockIdx.x * blockDim.x + threadIdx.x; i < nv; i += stride) {
        float4 v = x4[i];
        float r[4];
        float dv[4] = {v.x * c, v.y * c, v.z * c, v.w * c};
        #pragma unroll
        for (int k = 0; k < 4; ++k) {
            float d = dv[k];
            // exact searchsorted(grid, d, 'left')-1 clipped to [0,3]
            int seg = (d > g1) + (d > g2) + (d > g3);
            float index = s_accum[seg] + s_slope[seg] * (d - s_grid[seg]);
            float bf  = floorf(index);
            float pos = index - bf;
            int bi = (int)bf;
            int b  = min(max(bi, 0), P - 1);
            int e  = min(max(bi + 1, 0), P - 1);
            float omp = 1.0f - pos;
            float th = omp * s_tp[b] + pos * s_tp[e];
            float ve = omp * s_vp[b] + pos * s_vp[e];
            float sn, cs;
            sincosf(th, &sn, &cs);
            float val = d * (1.0f + ve * sn) + ve * cs;
            r[k] = val * sp;
        }
        o4[i] = make_float4(r[0], r[1], r[2], r[3]);
    }
    for (int i = (nv << 2) + blockIdx.x * blockDim.x + threadIdx.x; i < n; i += stride) {
        float d = x[i] * c;
        int seg = (d > g1) + (d > g2) + (d > g3);
        float index = s_accum[seg] + s_slope[seg] * (d - s_grid[seg]);
        float bf  = floorf(index);
        float pos = index - bf;
        int bi = (int)bf;
        int b  = min(max(bi, 0), P - 1);
        int e  = min(max(bi + 1, 0), P - 1);
        float omp = 1.0f - pos;
        float th = omp * s_tp[b] + pos * s_tp[e];
        float ve = omp * s_vp[b] + pos * s_vp[e];
        float sn, cs;
        sincosf(th, &sn, &cs);
        out[i] = (d * (1.0f + ve * sn) + ve * cs) * sp;
    }
}

// ---------------- launcher ----------------
extern "C" void kernel_launch(void* const* d_in, const int* in_sizes, int n_in,
                              void* d_out, int out_size) {
    const float* data   = (const float*)d_in[0];
    const float* params = (const float*)d_in[1];
    const float* ct     = (const float*)d_in[2];
    const float* st     = (const float*)d_in[3];
    float* out = (float*)d_out;
    const int n = in_sizes[0];

    const int threads = 256;
    int blocks = (n / 4 + threads - 1) / threads;
    if (blocks > 2368) blocks = 2368;   // 148 SMs * 16
    if (blocks < 1) blocks = 1;

    k_init<<<1, 32>>>();
    k_minmax<<<blocks, threads>>>(data, ct, n);
    k_setupA<<<1, 1>>>();
    k_hist<<<blocks, threads>>>(data, ct, n);
    k_setupB<<<1, 1>>>(params);
    k_compute<<<blocks, threads>>>(data, ct, st, out, n);
}

// round 4
// speedup vs baseline: 1.5174x; 1.5174x over previous
#include <cuda_runtime.h>

#define P 5

// ---------------- device scratch ----------------
__device__ unsigned g_min_key;
__device__ unsigned g_max_key;
__device__ int      g_ge[4];          // counts of d >= E_k, k=1..4
__device__ float    g_dmin, g_width;
// compute-pass tables
__device__ float2   g_AB[4];          // index = A[s] + B[s]*t
__device__ float4   g_CD[7];          // (Ct, Dt, Cv, Dv)[j]
__device__ float    g_invw, g_k0;     // t = d*invw - k0

// monotone key mapping for float atomics
__device__ __forceinline__ unsigned f2key(float f) {
    unsigned u = __float_as_uint(f);
    return (u & 0x80000000u) ? ~u : (u | 0x80000000u);
}
__device__ __forceinline__ float key2f(unsigned k) {
    unsigned u = (k & 0x80000000u) ? (k ^ 0x80000000u) : ~k;
    return __uint_as_float(u);
}

// ---------------- kernel 0: reset ----------------
__global__ void k_init() {
    if (threadIdx.x == 0) {
        g_min_key = 0xFFFFFFFFu;
        g_max_key = 0u;
    }
    if (threadIdx.x < 4) g_ge[threadIdx.x] = 0;
}

// ---------------- kernel 1: global min/max of raw x ----------------
__global__ void k_minmax(const float* __restrict__ x, int n) {
    float lo = __int_as_float(0x7f800000);
    float hi = __int_as_float(0xff800000);

    const int nv = n >> 2;
    const float4* __restrict__ x4 = (const float4*)x;
    const int stride = gridDim.x * blockDim.x;
    int i = blockIdx.x * blockDim.x + threadIdx.x;
    // 2x unrolled grid-stride
    for (; i + stride < nv; i += 2 * stride) {
        float4 a = x4[i];
        float4 b = x4[i + stride];
        lo = fminf(lo, fminf(fminf(a.x, a.y), fminf(a.z, a.w)));
        hi = fmaxf(hi, fmaxf(fmaxf(a.x, a.y), fmaxf(a.z, a.w)));
        lo = fminf(lo, fminf(fminf(b.x, b.y), fminf(b.z, b.w)));
        hi = fmaxf(hi, fmaxf(fmaxf(b.x, b.y), fmaxf(b.z, b.w)));
    }
    for (; i < nv; i += stride) {
        float4 a = x4[i];
        lo = fminf(lo, fminf(fminf(a.x, a.y), fminf(a.z, a.w)));
        hi = fmaxf(hi, fmaxf(fmaxf(a.x, a.y), fmaxf(a.z, a.w)));
    }
    for (int j = (nv << 2) + blockIdx.x * blockDim.x + threadIdx.x; j < n; j += stride) {
        float v = x[j];
        lo = fminf(lo, v);
        hi = fmaxf(hi, v);
    }

    #pragma unroll
    for (int o = 16; o; o >>= 1) {
        lo = fminf(lo, __shfl_xor_sync(0xFFFFFFFFu, lo, o));
        hi = fmaxf(hi, __shfl_xor_sync(0xFFFFFFFFu, hi, o));
    }
    __shared__ float s_lo[8], s_hi[8];
    const int wid = threadIdx.x >> 5, lid = threadIdx.x & 31;
    if (lid == 0) { s_lo[wid] = lo; s_hi[wid] = hi; }
    __syncthreads();
    if (threadIdx.x == 0) {
        const int nw = (blockDim.x + 31) >> 5;
        for (int w = 1; w < nw; ++w) {
            lo = fminf(lo, s_lo[w]);
            hi = fmaxf(hi, s_hi[w]);
        }
        atomicMin(&g_min_key, f2key(lo));
        atomicMax(&g_max_key, f2key(hi));
    }
}

// ---------------- kernel 2: dmin/width from scaled extrema ----------------
__global__ void k_setupA(const float* __restrict__ ct) {
    float c = ct[0];
    float a = c * key2f(g_min_key);
    float b = c * key2f(g_max_key);
    float mn = fminf(a, b);
    float mx = fmaxf(a, b);
    float dmin = mn - 0.1f;
    float dmax = mx + 0.1f;
    g_dmin = dmin;
    g_width = (dmax - dmin) / (float)P;
}

// ---------------- kernel 3: histogram via 4 threshold counters ----------------
__global__ void k_hist(const float* __restrict__ x,
                       const float* __restrict__ ct, int n) {
    const float c = ct[0];
    const float dmin = g_dmin;
    const float w = g_width;
    const float E1 = dmin + w, E2 = dmin + 2.0f * w,
                E3 = dmin + 3.0f * w, E4 = dmin + 4.0f * w;

    int n1 = 0, n2 = 0, n3 = 0, n4 = 0;

    const int nv = n >> 2;
    const float4* __restrict__ x4 = (const float4*)x;
    const int stride = gridDim.x * blockDim.x;
    int i = blockIdx.x * blockDim.x + threadIdx.x;
    for (; i + stride < nv; i += 2 * stride) {
        float4 a = x4[i];
        float4 b = x4[i + stride];
        float dv[8] = {a.x * c, a.y * c, a.z * c, a.w * c,
                       b.x * c, b.y * c, b.z * c, b.w * c};
        #pragma unroll
        for (int k = 0; k < 8; ++k) {
            float d = dv[k];
            n1 += (d >= E1); n2 += (d >= E2); n3 += (d >= E3); n4 += (d >= E4);
        }
    }
    for (; i < nv; i += stride) {
        float4 a = x4[i];
        float dv[4] = {a.x * c, a.y * c, a.z * c, a.w * c};
        #pragma unroll
        for (int k = 0; k < 4; ++k) {
            float d = dv[k];
            n1 += (d >= E1); n2 += (d >= E2); n3 += (d >= E3); n4 += (d >= E4);
        }
    }
    for (int j = (nv << 2) + blockIdx.x * blockDim.x + threadIdx.x; j < n; j += stride) {
        float d = x[j] * c;
        n1 += (d >= E1); n2 += (d >= E2); n3 += (d >= E3); n4 += (d >= E4);
    }

    #pragma unroll
    for (int o = 16; o; o >>= 1) {
        n1 += __shfl_xor_sync(0xFFFFFFFFu, n1, o);
        n2 += __shfl_xor_sync(0xFFFFFFFFu, n2, o);
        n3 += __shfl_xor_sync(0xFFFFFFFFu, n3, o);
        n4 += __shfl_xor_sync(0xFFFFFFFFu, n4, o);
    }
    __shared__ int sh[4];
    if (threadIdx.x < 4) sh[threadIdx.x] = 0;
    __syncthreads();
    if ((threadIdx.x & 31) == 0) {
        atomicAdd(&sh[0], n1);
        atomicAdd(&sh[1], n2);
        atomicAdd(&sh[2], n3);
        atomicAdd(&sh[3], n4);
    }
    __syncthreads();
    if (threadIdx.x < 4) atomicAdd(&g_ge[threadIdx.x], sh[threadIdx.x]);
}

// ---------------- kernel 4: build all compute-pass tables ----------------
__global__ void k_setupB(const float* __restrict__ params, int n) {
    const float dmin = g_dmin;
    const float width = g_width;

    // reconstruct bin counts; replicate fp32 scatter-add saturation at 2^24
    int ge1 = g_ge[0], ge2 = g_ge[1], ge3 = g_ge[2], ge4 = g_ge[3];
    int ci[P] = {n - ge1, ge1 - ge2, ge2 - ge3, ge3 - ge4, ge4};
    float cf[P];
    float tot = 0.0f;
    #pragma unroll
    for (int k = 0; k < P; ++k) {
        cf[k] = fminf((float)ci[k], 16777216.0f);
        tot += cf[k];
    }

    float accum[P];
    float run = 0.0f;
    #pragma unroll
    for (int k = 0; k < P; ++k) {
        run += cf[k] / tot;
        accum[k] = run * (float)P;
    }

    float grid[P];
    #pragma unroll
    for (int k = 0; k < P; ++k) {
        float e0 = dmin + width * (float)k;
        float e1 = dmin + width * (float)(k + 1);
        grid[k] = 0.5f * (e0 + e1);
    }

    // t = d*invw - k0 puts d in grid units: t = (d - grid[0]) / width
    float invw = 1.0f / width;
    g_invw = invw;
    g_k0 = grid[0] * invw;

    // index = accum[s] + (accum[s+1]-accum[s]) * (t - s) = A[s] + B[s]*t
    #pragma unroll
    for (int s = 0; s < 4; ++s) {
        float den = grid[s + 1] - grid[s];
        float slope = (accum[s + 1] - accum[s]) / den;   // per unit d
        float B = slope * width;                          // per unit t
        float A = accum[s] - B * (float)s;
        g_AB[s] = make_float2(A, B);
    }

    // frame = interp1d(accum, grid, arange(P)), flat-segment guard
    float frame[P];
    #pragma unroll
    for (int k = 0; k < P; ++k) {
        float q = (float)k;
        int j = 0;
        while (j < P && accum[j] < q) ++j;
        int idx = j - 1;
        idx = min(max(idx, 0), P - 2);
        float x0 = accum[idx], x1 = accum[idx + 1];
        float den = x1 - x0;
        if (den == 0.0f) den = 1.0f;
        frame[k] = grid[idx] + (grid[idx + 1] - grid[idx]) / den * (q - x0);
    }
    float tp[P], vp[P];
    #pragma unroll
    for (int k = 0; k < P; ++k) {
        tp[k] = frame[k] + 0.001f * params[k];
        vp[k] = frame[k] + 0.001f * params[P + k];
    }

    // affine pieces over j = clamp(floor(index)+1, 0, 6):
    //   j=0   : index < 0      -> b=e=0   -> const tp[0]
    //   j=1..4: bi=j-1 in [0,3]-> tp[bi] + (tp[bi+1]-tp[bi])*(index - bi)
    //   j=5,6 : bi >= 4        -> b=e=4   -> const tp[4]
    for (int j = 0; j < 7; ++j) {
        float Ct, Dt, Cv, Dv;
        if (j == 0)      { Ct = tp[0]; Dt = 0.0f; Cv = vp[0]; Dv = 0.0f; }
        else if (j >= 5) { Ct = tp[4]; Dt = 0.0f; Cv = vp[4]; Dv = 0.0f; }
        else {
            int bi = j - 1;
            float dt = tp[bi + 1] - tp[bi];
            float dv = vp[bi + 1] - vp[bi];
            Ct = tp[bi] - dt * (float)bi; Dt = dt;
            Cv = vp[bi] - dv * (float)bi; Dv = dv;
        }
        g_CD[j] = make_float4(Ct, Dt, Cv, Dv);
    }
}

// ---------------- kernel 5: fused final transform ----------------
__device__ __forceinline__ float eval_one(float d, float invw, float k0,
                                          const float2* sAB, const float4* sCD,
                                          float sp) {
    float t = fmaf(d, invw, -k0);
    int s = __float2int_rd(t);
    s = min(max(s, 0), 3);
    float2 ab = sAB[s];
    float index = fmaf(ab.y, t, ab.x);
    int j = __float2int_rd(index) + 1;
    j = min(max(j, 0), 6);
    float4 cd = sCD[j];
    float th = fmaf(cd.y, index, cd.x);
    float ve = fmaf(cd.w, index, cd.z);
    float sn, cs;
    __sincosf(th, &sn, &cs);
    // (d*(1 + ve*sn) + ve*cs) * sp
    float val = fmaf(d, fmaf(ve, sn, 1.0f), ve * cs);
    return val * sp;
}

__global__ void k_compute(const float* __restrict__ x,
                          const float* __restrict__ ct,
                          const float* __restrict__ st,
                          float* __restrict__ out, int n) {
    __shared__ float2 sAB[4];
    __shared__ float4 sCD[7];
    if (threadIdx.x < 4) sAB[threadIdx.x] = g_AB[threadIdx.x];
    if (threadIdx.x < 7) sCD[threadIdx.x] = g_CD[threadIdx.x];
    __syncthreads();

    const float c    = ct[0];
    const float sp   = st[0];
    const float invw = g_invw;
    const float k0   = g_k0;

    const int nv = n >> 2;
    const float4* __restrict__ x4 = (const float4*)x;
    float4* __restrict__ o4 = (float4*)out;
    const int stride = gridDim.x * blockDim.x;

    int i = blockIdx.x * blockDim.x + threadIdx.x;
    // 2x unrolled: two independent float4 chains per iteration for MLP
    for (; i + stride < nv; i += 2 * stride) {
        float4 va = x4[i];
        float4 vb = x4[i + stride];
        float4 ra, rb;
        ra.x = eval_one(va.x * c, invw, k0, sAB, sCD, sp);
        ra.y = eval_one(va.y * c, invw, k0, sAB, sCD, sp);
        ra.z = eval_one(va.z * c, invw, k0, sAB, sCD, sp);
        ra.w = eval_one(va.w * c, invw, k0, sAB, sCD, sp);
        rb.x = eval_one(vb.x * c, invw, k0, sAB, sCD, sp);
        rb.y = eval_one(vb.y * c, invw, k0, sAB, sCD, sp);
        rb.z = eval_one(vb.z * c, invw, k0, sAB, sCD, sp);
        rb.w = eval_one(vb.w * c, invw, k0, sAB, sCD, sp);
        o4[i] = ra;
        o4[i + stride] = rb;
    }
    for (; i < nv; i += stride) {
        float4 v = x4[i];
        float4 r;
        r.x = eval_one(v.x * c, invw, k0, sAB, sCD, sp);
        r.y = eval_one(v.y * c, invw, k0, sAB, sCD, sp);
        r.z = eval_one(v.z * c, invw, k0, sAB, sCD, sp);
        r.w = eval_one(v.w * c, invw, k0, sAB, sCD, sp);
        o4[i] = r;
    }
    for (int j2 = (nv << 2) + blockIdx.x * blockDim.x + threadIdx.x; j2 < n; j2 += stride) {
        out[j2] = eval_one(x[j2] * c, invw, k0, sAB, sCD, sp);
    }
}

// ---------------- launcher ----------------
extern "C" void kernel_launch(void* const* d_in, const int* in_sizes, int n_in,
                              void* d_out, int out_size) {
    const float* data   = (const float*)d_in[0];
    const float* params = (const float*)d_in[1];
    const float* ct     = (const float*)d_in[2];
    const float* st     = (const float*)d_in[3];
    float* out = (float*)d_out;
    const int n = in_sizes[0];

    const int threads = 256;
    int blocks = (n / 4 + threads - 1) / threads;
    if (blocks > 2368) blocks = 2368;
    if (blocks < 1) blocks = 1;

    k_init<<<1, 32>>>();
    k_minmax<<<blocks, threads>>>(data, n);
    k_setupA<<<1, 1>>>(ct);
    k_hist<<<blocks, threads>>>(data, ct, n);
    k_setupB<<<1, 1>>>(params, n);
    k_compute<<<blocks, threads>>>(data, ct, st, out, n);
}